// round 3
// baseline (speedup 1.0000x reference)
#include <cuda_runtime.h>
#include <math.h>

#define NNODES 100000
#define BATCH  4096
#define MDIM   256
#define G3DIM  768
#define INENC  515
#define NT     512
#define TM     16
#define BK     16   // per-node bucket capacity (max node multiplicity is ~5 for this data)

// ---------------- device scratch (re-initialized every launch; graph-replay safe) ----
__device__ float    g_lu[NNODES];
__device__ int      g_ncnt[NNODES];
__device__ int      g_nbuck[NNODES * BK];
__device__ int      g_pred[2 * BATCH];
__device__ int      g_evlist[BATCH];
__device__ int      g_lvl_start[BATCH + 2];
__device__ int      g_nlevels;
__device__ unsigned g_bar_count = 0;
__device__ unsigned g_bar_gen   = 0;

// ---------------- software grid barrier (all blocks resident: 1 block/SM) -----------
__device__ __forceinline__ void grid_sync() {
    __syncthreads();
    if (threadIdx.x == 0) {
        __threadfence();
        unsigned gen = *((volatile unsigned*)&g_bar_gen);
        if (atomicAdd(&g_bar_count, 1u) == gridDim.x - 1u) {
            *((volatile unsigned*)&g_bar_count) = 0u;
            __threadfence();
            atomicAdd(&g_bar_gen, 1u);
        } else {
            while (*((volatile unsigned*)&g_bar_gen) == gen) { __nanosleep(128); }
        }
        __threadfence();
    }
    __syncthreads();
}

// ---------------- shared memory layout ----------------------------------------------
struct TileS {
    float Xs[TM][MDIM];    // decayed prev state of src
    float Xd[TM][MDIM];    // decayed prev state of dst
    float H1[TM][MDIM];
    float MSG[TM][MDIM];
    float GI[TM][G3DIM];   // x @ w_ih^T + b_ih (shared by both GRU calls)
    float EF[TM][4];
    float T[TM]; float Fs[TM]; float Fd[TM];
    int   S[TM]; int D[TM]; int EV[TM];
};
struct LvlS {
    int level[BATCH];
    int off[BATCH + 2];
    int cnt[BATCH + 2];
    int maxl;
    int changed;
};
#define SMEM_BYTES ((int)sizeof(TileS))

extern __shared__ __align__(16) char smem_raw[];

__device__ __forceinline__ float sigmoidf_(float x) { return 1.0f / (1.0f + expf(-x)); }

__global__ void __launch_bounds__(NT, 1)
tgn_kernel(const int* __restrict__ src, const int* __restrict__ dst,
           const float* __restrict__ ef, const int* __restrict__ ts,
           const float* __restrict__ mem0, const float* __restrict__ lu0,
           const float* __restrict__ W1, const float* __restrict__ b1,
           const float* __restrict__ W2, const float* __restrict__ b2,
           const float* __restrict__ wih, const float* __restrict__ bih,
           const float* __restrict__ whh, const float* __restrict__ bhh,
           float* __restrict__ out)
{
    const int tid     = threadIdx.x;
    const int gtid    = blockIdx.x * NT + tid;
    const int gstride = gridDim.x * NT;

    // ---------- Phase A: copy memory -> out, last_update -> g_lu, zero node counters
    {
        const float4* s4 = (const float4*)mem0;
        float4*       d4 = (float4*)out;
        const int n4 = NNODES * MDIM / 4;
        for (int i = gtid; i < n4; i += gstride) d4[i] = s4[i];
        for (int i = gtid; i < NNODES; i += gstride) { g_lu[i] = lu0[i]; g_ncnt[i] = 0; }
    }
    grid_sync();

    // ---------- Phase A2: per-node occurrence buckets (unordered; order fixed later)
    for (int i = gtid; i < 2 * BATCH; i += gstride) {
        int e = i >> 1;
        int v = (i & 1) ? dst[e] : src[e];
        int slot = atomicAdd(&g_ncnt[v], 1);
        if (slot < BK) g_nbuck[v * BK + slot] = i;
    }
    grid_sync();

    // ---------- Phase A3: predecessor endpoint (latest endpoint of a strictly earlier event)
    for (int i = gtid; i < 2 * BATCH; i += gstride) {
        int e = i >> 1;
        int v = (i & 1) ? dst[e] : src[e];
        int lim = e << 1;                     // endpoints of events < e are < lim
        int c = g_ncnt[v]; if (c > BK) c = BK;
        int p = -1;
        for (int t = 0; t < c; t++) {
            int j = g_nbuck[v * BK + t];
            if (j < lim && j > p) p = j;
        }
        g_pred[i] = p;
    }
    grid_sync();

    // ---------- Phase B (block 0): levelization + counting sort by level
    if (blockIdx.x == 0) {
        LvlS* L = (LvlS*)smem_raw;
        for (int e = tid; e < BATCH; e += NT) L->level[e] = 0;
        if (tid == 0) L->maxl = 0;
        __syncthreads();
        for (;;) {
            if (tid == 0) L->changed = 0;
            __syncthreads();
            for (int e = tid; e < BATCH; e += NT) {
                int ps = g_pred[2 * e], pd = g_pred[2 * e + 1];
                int lv = 0;
                if (ps >= 0) { int t = L->level[ps >> 1] + 1; if (t > lv) lv = t; }
                if (pd >= 0) { int t = L->level[pd >> 1] + 1; if (t > lv) lv = t; }
                if (lv > L->level[e]) { L->level[e] = lv; L->changed = 1; }
            }
            __syncthreads();
            int ch = L->changed;
            __syncthreads();
            if (!ch) break;
        }
        for (int e = tid; e < BATCH; e += NT) atomicMax(&L->maxl, L->level[e]);
        __syncthreads();
        int nl = L->maxl + 1;
        for (int i = tid; i < nl + 1; i += NT) L->cnt[i] = 0;
        __syncthreads();
        for (int e = tid; e < BATCH; e += NT) atomicAdd(&L->cnt[L->level[e]], 1);
        __syncthreads();
        if (tid == 0) {
            int acc = 0;
            for (int l = 0; l < nl; l++) { L->off[l] = acc; acc += L->cnt[l]; }
            L->off[nl] = acc;
            g_nlevels = nl;
            for (int l = 0; l <= nl; l++) g_lvl_start[l] = L->off[l];
        }
        __syncthreads();
        for (int i = tid; i < nl; i += NT) L->cnt[i] = 0;
        __syncthreads();
        for (int e = tid; e < BATCH; e += NT) {
            int l = L->level[e];
            int pos = L->off[l] + atomicAdd(&L->cnt[l], 1);
            g_evlist[pos] = e;
        }
    }
    grid_sync();

    // ---------- Phase C: process levels; each block owns TM-event tiles end-to-end
    const int nlevels = g_nlevels;
    TileS* Tq = (TileS*)smem_raw;

    for (int lvl = 0; lvl < nlevels; lvl++) {
        const int lvS = g_lvl_start[lvl];
        const int lvE = g_lvl_start[lvl + 1];
        const int nE  = lvE - lvS;
        const int ntiles = (nE + TM - 1) / TM;

        for (int tile = blockIdx.x; tile < ntiles; tile += gridDim.x) {
            const int base = lvS + tile * TM;
            const int cnt  = min(TM, lvE - base);

            // ---- event metadata + decay factors
            if (tid < TM) {
                int m = tid;
                if (m < cnt) {
                    int e = g_evlist[base + m];
                    int s = src[e], d = dst[e];
                    float t  = (float)ts[e];
                    float fs = expf(-0.1f * fmaxf(t - g_lu[s], 0.0f));
                    float fd = expf(-0.1f * fmaxf(t - g_lu[d], 0.0f));
                    Tq->S[m] = s; Tq->D[m] = d; Tq->EV[m] = e;
                    Tq->T[m] = t; Tq->Fs[m] = fs; Tq->Fd[m] = fd;
                } else {
                    Tq->S[m] = 0; Tq->D[m] = 0; Tq->EV[m] = 0;
                    Tq->T[m] = 0.f; Tq->Fs[m] = 0.f; Tq->Fd[m] = 0.f;
                }
            }
            __syncthreads();

            // ---- gather decayed states (warp per event)
            {
                int m = tid >> 5, lane = tid & 31;
                if (m < cnt) {
                    int s = Tq->S[m], d = Tq->D[m];
                    float fs = Tq->Fs[m], fd = Tq->Fd[m];
                    const float* rs = out + (size_t)s * MDIM;
                    const float* rd = out + (size_t)d * MDIM;
                    for (int c = lane; c < MDIM; c += 32) {
                        Tq->Xs[m][c] = rs[c] * fs;
                        Tq->Xd[m][c] = rd[c] * fd;
                    }
                    if (lane < 3) Tq->EF[m][lane] = ef[(size_t)Tq->EV[m] * 3 + lane];
                    if (lane == 3) Tq->EF[m][3] = 0.f;
                } else {
                    for (int c = lane; c < MDIM; c += 32) { Tq->Xs[m][c] = 0.f; Tq->Xd[m][c] = 0.f; }
                    if (lane < 4) Tq->EF[m][lane] = 0.f;
                }
            }
            __syncthreads();

            // ---- H1 = relu([Xs|Xd|ef] @ W1^T + b1)
            {
                int c = tid & (MDIM - 1);
                int g = tid >> 8;
                int m0 = g * 8;
                float acc[8];
                float bb = b1[c];
                #pragma unroll
                for (int r = 0; r < 8; r++) acc[r] = bb;
                const float* w = W1 + (size_t)c * INENC;
                #pragma unroll 4
                for (int k = 0; k < MDIM; k++) {
                    float wv = w[k];
                    #pragma unroll
                    for (int r = 0; r < 8; r++) acc[r] = fmaf(Tq->Xs[m0 + r][k], wv, acc[r]);
                }
                #pragma unroll 4
                for (int k = 0; k < MDIM; k++) {
                    float wv = w[MDIM + k];
                    #pragma unroll
                    for (int r = 0; r < 8; r++) acc[r] = fmaf(Tq->Xd[m0 + r][k], wv, acc[r]);
                }
                #pragma unroll
                for (int k = 0; k < 3; k++) {
                    float wv = w[2 * MDIM + k];
                    #pragma unroll
                    for (int r = 0; r < 8; r++) acc[r] = fmaf(Tq->EF[m0 + r][k], wv, acc[r]);
                }
                #pragma unroll
                for (int r = 0; r < 8; r++) Tq->H1[m0 + r][c] = fmaxf(acc[r], 0.f);
            }
            __syncthreads();

            // ---- MSG = H1 @ W2^T + b2
            {
                int c = tid & (MDIM - 1);
                int g = tid >> 8;
                int m0 = g * 8;
                float acc[8];
                float bb = b2[c];
                #pragma unroll
                for (int r = 0; r < 8; r++) acc[r] = bb;
                const float* w = W2 + (size_t)c * MDIM;
                #pragma unroll 4
                for (int k = 0; k < MDIM; k++) {
                    float wv = w[k];
                    #pragma unroll
                    for (int r = 0; r < 8; r++) acc[r] = fmaf(Tq->H1[m0 + r][k], wv, acc[r]);
                }
                #pragma unroll
                for (int r = 0; r < 8; r++) Tq->MSG[m0 + r][c] = acc[r];
            }
            __syncthreads();

            // ---- GI = MSG @ w_ih^T + b_ih  (768 outputs/row; shared by both GRU calls)
            #pragma unroll
            for (int pass = 0; pass < 2; pass++) {
                int c = pass * NT + tid;
                if (c < G3DIM) {
                    float acc[TM];
                    float bb = bih[c];
                    #pragma unroll
                    for (int m = 0; m < TM; m++) acc[m] = bb;
                    const float* w = wih + (size_t)c * MDIM;
                    #pragma unroll 4
                    for (int k = 0; k < MDIM; k++) {
                        float wv = w[k];
                        #pragma unroll
                        for (int m = 0; m < TM; m++) acc[m] = fmaf(Tq->MSG[m][k], wv, acc[m]);
                    }
                    #pragma unroll
                    for (int m = 0; m < TM; m++) Tq->GI[m][c] = acc[m];
                }
            }
            __syncthreads();

            // ---- GH (on the fly) + GRU elementwise + scatter
            {
                int j = tid & (MDIM - 1);
                int g = tid >> 8;
                const float* wr = whh + (size_t)j * MDIM;
                const float* wz = whh + (size_t)(MDIM + j) * MDIM;
                const float* wn = whh + (size_t)(2 * MDIM + j) * MDIM;
                float br = bhh[j], bz = bhh[MDIM + j], bn = bhh[2 * MDIM + j];
                #pragma unroll
                for (int half = 0; half < 2; half++) {
                    int m0 = g * 8 + half * 4;
                    float ars[4], azs[4], ans[4], ard[4], azd[4], and_[4];
                    #pragma unroll
                    for (int r = 0; r < 4; r++) {
                        ars[r] = br; azs[r] = bz; ans[r] = bn;
                        ard[r] = br; azd[r] = bz; and_[r] = bn;
                    }
                    #pragma unroll 2
                    for (int k = 0; k < MDIM; k++) {
                        float wrv = wr[k], wzv = wz[k], wnv = wn[k];
                        #pragma unroll
                        for (int r = 0; r < 4; r++) {
                            float xs = Tq->Xs[m0 + r][k];
                            float xd = Tq->Xd[m0 + r][k];
                            ars[r]  = fmaf(xs, wrv, ars[r]);
                            azs[r]  = fmaf(xs, wzv, azs[r]);
                            ans[r]  = fmaf(xs, wnv, ans[r]);
                            ard[r]  = fmaf(xd, wrv, ard[r]);
                            azd[r]  = fmaf(xd, wzv, azd[r]);
                            and_[r] = fmaf(xd, wnv, and_[r]);
                        }
                    }
                    #pragma unroll
                    for (int r = 0; r < 4; r++) {
                        int m = m0 + r;
                        if (m < cnt) {
                            float gir = Tq->GI[m][j];
                            float giz = Tq->GI[m][MDIM + j];
                            float gin = Tq->GI[m][2 * MDIM + j];
                            float hs = Tq->Xs[m][j];
                            float hd = Tq->Xd[m][j];
                            float rr = sigmoidf_(gir + ars[r]);
                            float zz = sigmoidf_(giz + azs[r]);
                            float nn = tanhf(gin + rr * ans[r]);
                            float us = (1.0f - zz) * nn + zz * hs;
                            rr = sigmoidf_(gir + ard[r]);
                            zz = sigmoidf_(giz + azd[r]);
                            nn = tanhf(gin + rr * and_[r]);
                            float ud = (1.0f - zz) * nn + zz * hd;
                            int s = Tq->S[m], d = Tq->D[m];
                            if (s != d) out[(size_t)s * MDIM + j] = us;   // dst wins on s==d
                            out[(size_t)d * MDIM + j] = ud;
                        }
                    }
                }
            }
            // ---- last_update
            if (tid < cnt) {
                g_lu[Tq->S[tid]] = Tq->T[tid];
                g_lu[Tq->D[tid]] = Tq->T[tid];
            }
            __syncthreads();
        }
        grid_sync();   // level boundary: make mem/lu writes visible to next level's gathers
    }
}

extern "C" void kernel_launch(void* const* d_in, const int* in_sizes, int n_in,
                              void* d_out, int out_size)
{
    const int*   src  = (const int*)  d_in[0];
    const int*   dst  = (const int*)  d_in[1];
    const float* ef   = (const float*)d_in[2];
    const int*   ts   = (const int*)  d_in[3];
    const float* mem0 = (const float*)d_in[4];
    const float* lu0  = (const float*)d_in[5];
    const float* W1   = (const float*)d_in[6];
    const float* b1   = (const float*)d_in[7];
    const float* W2   = (const float*)d_in[8];
    const float* b2   = (const float*)d_in[9];
    const float* wih  = (const float*)d_in[10];   // w_ih  (3H, MSG)
    const float* whh  = (const float*)d_in[11];   // w_hh  (3H, H)   <-- fixed order
    const float* bih  = (const float*)d_in[12];   // b_ih  (3H,)     <-- fixed order
    const float* bhh  = (const float*)d_in[13];   // b_hh  (3H,)
    float* out = (float*)d_out;

    int dev = 0, sms = 148;
    cudaGetDevice(&dev);
    cudaDeviceGetAttribute(&sms, cudaDevAttrMultiProcessorCount, dev);
    if (sms <= 0) sms = 148;

    cudaFuncSetAttribute(tgn_kernel, cudaFuncAttributeMaxDynamicSharedMemorySize, SMEM_BYTES);

    tgn_kernel<<<sms, NT, SMEM_BYTES>>>(src, dst, ef, ts, mem0, lu0,
                                        W1, b1, W2, b2, wih, bih, whh, bhh, out);
}

// round 4
// speedup vs baseline: 4.6991x; 4.6991x over previous
#include <cuda_runtime.h>
#include <math.h>

#define NNODES 100000
#define BATCH  4096
#define MDIM   256
#define G3DIM  768
#define INENC  515
#define NT     512
#define TM     16
#define BK     16

// ---------------- device scratch (re-initialized every launch; graph-replay safe) ----
__device__ float    g_lu[NNODES];
__device__ int      g_ncnt[NNODES];
__device__ int      g_nbuck[NNODES * BK];
__device__ int      g_pred[2 * BATCH];
__device__ int      g_evlist[BATCH];
__device__ int      g_lvl_start[BATCH + 2];
__device__ int      g_nlevels;
__device__ unsigned g_bar_count = 0;
__device__ unsigned g_bar_gen   = 0;

// transposed+packed weights: layout [k4][c][4]  (float4 per (k4,c))
__device__ float g_W1tA[MDIM  * MDIM];    // W1 cols [0,256)   : [64][256][4]
__device__ float g_W1tB[MDIM  * MDIM];    // W1 cols [256,512) : [64][256][4]
__device__ float g_W2t [MDIM  * MDIM];    // [64][256][4]
__device__ float g_wiht[G3DIM * MDIM];    // [64][768][4]
__device__ float g_whht[G3DIM * MDIM];    // [64][768][4]

// ---------------- software grid barrier (1 block/SM) --------------------------------
__device__ __forceinline__ void grid_sync() {
    __syncthreads();
    if (threadIdx.x == 0) {
        __threadfence();
        unsigned gen = *((volatile unsigned*)&g_bar_gen);
        if (atomicAdd(&g_bar_count, 1u) == gridDim.x - 1u) {
            *((volatile unsigned*)&g_bar_count) = 0u;
            __threadfence();
            atomicAdd(&g_bar_gen, 1u);
        } else {
            while (*((volatile unsigned*)&g_bar_gen) == gen) { __nanosleep(128); }
        }
        __threadfence();
    }
    __syncthreads();
}

// ---------------- shared memory layouts ---------------------------------------------
struct TileS {
    float Xs[TM][MDIM];
    float Xd[TM][MDIM];
    float H1[TM][MDIM];
    float MSG[TM][MDIM];
    float GI[TM][G3DIM];
    float EF[TM][4];
    float T[TM]; float Fs[TM]; float Fd[TM];
    int   S[TM]; int D[TM]; int EV[TM];
};
struct LvlS {
    int level[BATCH];
    int off[BATCH + 2];
    int cnt[BATCH + 2];
    int maxl;
    int changed;
};
#define SMEM_BYTES ((int)sizeof(TileS))

extern __shared__ __align__(16) char smem_raw[];

__device__ __forceinline__ float sigmoidf_(float x) { return 1.0f / (1.0f + expf(-x)); }

__device__ __forceinline__ float dot4(float4 a, float4 b, float acc) {
    acc = fmaf(a.x, b.x, acc);
    acc = fmaf(a.y, b.y, acc);
    acc = fmaf(a.z, b.z, acc);
    acc = fmaf(a.w, b.w, acc);
    return acc;
}

__global__ void __launch_bounds__(NT, 1)
tgn_kernel(const int* __restrict__ src, const int* __restrict__ dst,
           const float* __restrict__ ef, const int* __restrict__ ts,
           const float* __restrict__ mem0, const float* __restrict__ lu0,
           const float* __restrict__ W1, const float* __restrict__ b1,
           const float* __restrict__ W2, const float* __restrict__ b2,
           const float* __restrict__ wih, const float* __restrict__ bih,
           const float* __restrict__ whh, const float* __restrict__ bhh,
           float* __restrict__ out)
{
    const int tid     = threadIdx.x;
    const int gtid    = blockIdx.x * NT + tid;
    const int gstride = gridDim.x * NT;

    // ---------- Phase A: copy memory -> out, lu -> g_lu, weight transposes ----------
    {
        const float4* s4 = (const float4*)mem0;
        float4*       d4 = (float4*)out;
        const int n4 = NNODES * MDIM / 4;
        for (int i = gtid; i < n4; i += gstride) d4[i] = s4[i];
        for (int i = gtid; i < NNODES; i += gstride) { g_lu[i] = lu0[i]; g_ncnt[i] = 0; }

        // transpose+pack: dst index i -> k4 = i/(C*4), c = (i%(C*4))>>2, ks = i&3
        for (int i = gtid; i < MDIM * MDIM; i += gstride) {
            int k4 = i >> 10, rem = i & 1023, c = rem >> 2, ks = rem & 3;
            int k = k4 * 4 + ks;
            g_W1tA[i] = W1[(size_t)c * INENC + k];
            g_W1tB[i] = W1[(size_t)c * INENC + MDIM + k];
            g_W2t[i]  = W2[(size_t)c * MDIM + k];
        }
        for (int i = gtid; i < G3DIM * MDIM; i += gstride) {
            int k4 = i / 3072, rem = i - k4 * 3072, c = rem >> 2, ks = rem & 3;
            int k = k4 * 4 + ks;
            g_wiht[i] = wih[(size_t)c * MDIM + k];
            g_whht[i] = whh[(size_t)c * MDIM + k];
        }
    }
    grid_sync();

    // ---------- Phase A2: per-node occurrence buckets --------------------------------
    for (int i = gtid; i < 2 * BATCH; i += gstride) {
        int e = i >> 1;
        int v = (i & 1) ? dst[e] : src[e];
        int slot = atomicAdd(&g_ncnt[v], 1);
        if (slot < BK) g_nbuck[v * BK + slot] = i;
    }
    grid_sync();

    // ---------- Phase A3: predecessor endpoint ---------------------------------------
    for (int i = gtid; i < 2 * BATCH; i += gstride) {
        int e = i >> 1;
        int v = (i & 1) ? dst[e] : src[e];
        int lim = e << 1;
        int c = g_ncnt[v]; if (c > BK) c = BK;
        int p = -1;
        for (int t = 0; t < c; t++) {
            int j = g_nbuck[v * BK + t];
            if (j < lim && j > p) p = j;
        }
        g_pred[i] = p;
    }
    grid_sync();

    // ---------- Phase B (block 0): levelization + counting sort ----------------------
    if (blockIdx.x == 0) {
        LvlS* L = (LvlS*)smem_raw;
        for (int e = tid; e < BATCH; e += NT) L->level[e] = 0;
        if (tid == 0) L->maxl = 0;
        __syncthreads();
        for (;;) {
            if (tid == 0) L->changed = 0;
            __syncthreads();
            for (int e = tid; e < BATCH; e += NT) {
                int ps = g_pred[2 * e], pd = g_pred[2 * e + 1];
                int lv = 0;
                if (ps >= 0) { int t = L->level[ps >> 1] + 1; if (t > lv) lv = t; }
                if (pd >= 0) { int t = L->level[pd >> 1] + 1; if (t > lv) lv = t; }
                if (lv > L->level[e]) { L->level[e] = lv; L->changed = 1; }
            }
            __syncthreads();
            int ch = L->changed;
            __syncthreads();
            if (!ch) break;
        }
        for (int e = tid; e < BATCH; e += NT) atomicMax(&L->maxl, L->level[e]);
        __syncthreads();
        int nl = L->maxl + 1;
        for (int i = tid; i < nl + 1; i += NT) L->cnt[i] = 0;
        __syncthreads();
        for (int e = tid; e < BATCH; e += NT) atomicAdd(&L->cnt[L->level[e]], 1);
        __syncthreads();
        if (tid == 0) {
            int acc = 0;
            for (int l = 0; l < nl; l++) { L->off[l] = acc; acc += L->cnt[l]; }
            L->off[nl] = acc;
            g_nlevels = nl;
            for (int l = 0; l <= nl; l++) g_lvl_start[l] = L->off[l];
        }
        __syncthreads();
        for (int i = tid; i < nl; i += NT) L->cnt[i] = 0;
        __syncthreads();
        for (int e = tid; e < BATCH; e += NT) {
            int l = L->level[e];
            int pos = L->off[l] + atomicAdd(&L->cnt[l], 1);
            g_evlist[pos] = e;
        }
    }
    grid_sync();

    // ---------- Phase C: levels; each block owns TM-event tiles end-to-end -----------
    const int nlevels = g_nlevels;
    TileS* Tq = (TileS*)smem_raw;

    const float4* w1a4 = (const float4*)g_W1tA;   // [k4*256 + c]
    const float4* w1b4 = (const float4*)g_W1tB;
    const float4* w24  = (const float4*)g_W2t;
    const float4* wih4 = (const float4*)g_wiht;   // [k4*768 + c]
    const float4* whh4 = (const float4*)g_whht;

    for (int lvl = 0; lvl < nlevels; lvl++) {
        const int lvS = g_lvl_start[lvl];
        const int lvE = g_lvl_start[lvl + 1];
        const int nE  = lvE - lvS;
        const int ntiles = (nE + TM - 1) / TM;

        for (int tile = blockIdx.x; tile < ntiles; tile += gridDim.x) {
            const int base = lvS + tile * TM;
            const int cnt  = min(TM, lvE - base);

            // ---- event metadata + decay factors
            if (tid < TM) {
                int m = tid;
                if (m < cnt) {
                    int e = g_evlist[base + m];
                    int s = src[e], d = dst[e];
                    float t  = (float)ts[e];
                    float fs = expf(-0.1f * fmaxf(t - g_lu[s], 0.0f));
                    float fd = expf(-0.1f * fmaxf(t - g_lu[d], 0.0f));
                    Tq->S[m] = s; Tq->D[m] = d; Tq->EV[m] = e;
                    Tq->T[m] = t; Tq->Fs[m] = fs; Tq->Fd[m] = fd;
                } else {
                    Tq->S[m] = 0; Tq->D[m] = 0; Tq->EV[m] = 0;
                    Tq->T[m] = 0.f; Tq->Fs[m] = 0.f; Tq->Fd[m] = 0.f;
                }
            }
            __syncthreads();

            // ---- gather decayed states (warp per event)
            {
                int m = tid >> 5, lane = tid & 31;
                if (m < cnt) {
                    int s = Tq->S[m], d = Tq->D[m];
                    float fs = Tq->Fs[m], fd = Tq->Fd[m];
                    const float* rs = out + (size_t)s * MDIM;
                    const float* rd = out + (size_t)d * MDIM;
                    for (int c = lane; c < MDIM; c += 32) {
                        Tq->Xs[m][c] = rs[c] * fs;
                        Tq->Xd[m][c] = rd[c] * fd;
                    }
                    if (lane < 3) Tq->EF[m][lane] = ef[(size_t)Tq->EV[m] * 3 + lane];
                    if (lane == 3) Tq->EF[m][3] = 0.f;
                } else {
                    for (int c = lane; c < MDIM; c += 32) { Tq->Xs[m][c] = 0.f; Tq->Xd[m][c] = 0.f; }
                    if (lane < 4) Tq->EF[m][lane] = 0.f;
                }
            }
            __syncthreads();

            // ---- H1 = relu([Xs|Xd|ef] @ W1^T + b1)   (coalesced packed weights)
            {
                int c = tid & (MDIM - 1);
                int g = tid >> 8;
                int m0 = g * 8;
                float acc[8];
                float bb = b1[c];
                #pragma unroll
                for (int r = 0; r < 8; r++) acc[r] = bb;

                const float4* xs4[8];
                #pragma unroll
                for (int r = 0; r < 8; r++) xs4[r] = (const float4*)Tq->Xs[m0 + r];
                #pragma unroll 4
                for (int k4 = 0; k4 < MDIM / 4; k4++) {
                    float4 wv = w1a4[k4 * MDIM + c];
                    #pragma unroll
                    for (int r = 0; r < 8; r++) acc[r] = dot4(xs4[r][k4], wv, acc[r]);
                }
                const float4* xd4[8];
                #pragma unroll
                for (int r = 0; r < 8; r++) xd4[r] = (const float4*)Tq->Xd[m0 + r];
                #pragma unroll 4
                for (int k4 = 0; k4 < MDIM / 4; k4++) {
                    float4 wv = w1b4[k4 * MDIM + c];
                    #pragma unroll
                    for (int r = 0; r < 8; r++) acc[r] = dot4(xd4[r][k4], wv, acc[r]);
                }
                // edge-feature tail (3 scalar weights from original W1)
                const float* we = W1 + (size_t)c * INENC + 2 * MDIM;
                #pragma unroll
                for (int k = 0; k < 3; k++) {
                    float wv = we[k];
                    #pragma unroll
                    for (int r = 0; r < 8; r++) acc[r] = fmaf(Tq->EF[m0 + r][k], wv, acc[r]);
                }
                #pragma unroll
                for (int r = 0; r < 8; r++) Tq->H1[m0 + r][c] = fmaxf(acc[r], 0.f);
            }
            __syncthreads();

            // ---- MSG = H1 @ W2^T + b2
            {
                int c = tid & (MDIM - 1);
                int g = tid >> 8;
                int m0 = g * 8;
                float acc[8];
                float bb = b2[c];
                #pragma unroll
                for (int r = 0; r < 8; r++) acc[r] = bb;
                const float4* h4[8];
                #pragma unroll
                for (int r = 0; r < 8; r++) h4[r] = (const float4*)Tq->H1[m0 + r];
                #pragma unroll 4
                for (int k4 = 0; k4 < MDIM / 4; k4++) {
                    float4 wv = w24[k4 * MDIM + c];
                    #pragma unroll
                    for (int r = 0; r < 8; r++) acc[r] = dot4(h4[r][k4], wv, acc[r]);
                }
                #pragma unroll
                for (int r = 0; r < 8; r++) Tq->MSG[m0 + r][c] = acc[r];
            }
            __syncthreads();

            // ---- GI = MSG @ w_ih^T + b_ih  (768 outputs/row)
            #pragma unroll
            for (int pass = 0; pass < 2; pass++) {
                int c = pass * NT + tid;
                if (c < G3DIM) {
                    float acc[TM];
                    float bb = bih[c];
                    #pragma unroll
                    for (int m = 0; m < TM; m++) acc[m] = bb;
                    #pragma unroll 2
                    for (int k4 = 0; k4 < MDIM / 4; k4++) {
                        float4 wv = wih4[k4 * G3DIM + c];
                        #pragma unroll
                        for (int m = 0; m < TM; m++) {
                            float4 x = ((const float4*)Tq->MSG[m])[k4];
                            acc[m] = dot4(x, wv, acc[m]);
                        }
                    }
                    #pragma unroll
                    for (int m = 0; m < TM; m++) Tq->GI[m][c] = acc[m];
                }
            }
            __syncthreads();

            // ---- GH (on the fly) + GRU elementwise + scatter
            {
                int j = tid & (MDIM - 1);
                int g = tid >> 8;
                float br = bhh[j], bz = bhh[MDIM + j], bn = bhh[2 * MDIM + j];
                #pragma unroll
                for (int half = 0; half < 2; half++) {
                    int m0 = g * 8 + half * 4;
                    float ars[4], azs[4], ans[4], ard[4], azd[4], and_[4];
                    #pragma unroll
                    for (int r = 0; r < 4; r++) {
                        ars[r] = br; azs[r] = bz; ans[r] = bn;
                        ard[r] = br; azd[r] = bz; and_[r] = bn;
                    }
                    const float4* xs4[4];
                    const float4* xd4[4];
                    #pragma unroll
                    for (int r = 0; r < 4; r++) {
                        xs4[r] = (const float4*)Tq->Xs[m0 + r];
                        xd4[r] = (const float4*)Tq->Xd[m0 + r];
                    }
                    for (int k4 = 0; k4 < MDIM / 4; k4++) {
                        float4 wrv = whh4[k4 * G3DIM + j];
                        float4 wzv = whh4[k4 * G3DIM + MDIM + j];
                        float4 wnv = whh4[k4 * G3DIM + 2 * MDIM + j];
                        #pragma unroll
                        for (int r = 0; r < 4; r++) {
                            float4 xs = xs4[r][k4];
                            float4 xd = xd4[r][k4];
                            ars[r]  = dot4(xs, wrv, ars[r]);
                            azs[r]  = dot4(xs, wzv, azs[r]);
                            ans[r]  = dot4(xs, wnv, ans[r]);
                            ard[r]  = dot4(xd, wrv, ard[r]);
                            azd[r]  = dot4(xd, wzv, azd[r]);
                            and_[r] = dot4(xd, wnv, and_[r]);
                        }
                    }
                    #pragma unroll
                    for (int r = 0; r < 4; r++) {
                        int m = m0 + r;
                        if (m < cnt) {
                            float gir = Tq->GI[m][j];
                            float giz = Tq->GI[m][MDIM + j];
                            float gin = Tq->GI[m][2 * MDIM + j];
                            float hs = Tq->Xs[m][j];
                            float hd = Tq->Xd[m][j];
                            float rr = sigmoidf_(gir + ars[r]);
                            float zz = sigmoidf_(giz + azs[r]);
                            float nn = tanhf(gin + rr * ans[r]);
                            float us = (1.0f - zz) * nn + zz * hs;
                            rr = sigmoidf_(gir + ard[r]);
                            zz = sigmoidf_(giz + azd[r]);
                            nn = tanhf(gin + rr * and_[r]);
                            float ud = (1.0f - zz) * nn + zz * hd;
                            int s = Tq->S[m], d = Tq->D[m];
                            if (s != d) out[(size_t)s * MDIM + j] = us;   // dst wins on s==d
                            out[(size_t)d * MDIM + j] = ud;
                        }
                    }
                }
            }
            // ---- last_update
            if (tid < cnt) {
                g_lu[Tq->S[tid]] = Tq->T[tid];
                g_lu[Tq->D[tid]] = Tq->T[tid];
            }
            __syncthreads();
        }
        grid_sync();
    }
}

extern "C" void kernel_launch(void* const* d_in, const int* in_sizes, int n_in,
                              void* d_out, int out_size)
{
    const int*   src  = (const int*)  d_in[0];
    const int*   dst  = (const int*)  d_in[1];
    const float* ef   = (const float*)d_in[2];
    const int*   ts   = (const int*)  d_in[3];
    const float* mem0 = (const float*)d_in[4];
    const float* lu0  = (const float*)d_in[5];
    const float* W1   = (const float*)d_in[6];
    const float* b1   = (const float*)d_in[7];
    const float* W2   = (const float*)d_in[8];
    const float* b2   = (const float*)d_in[9];
    const float* wih  = (const float*)d_in[10];
    const float* whh  = (const float*)d_in[11];
    const float* bih  = (const float*)d_in[12];
    const float* bhh  = (const float*)d_in[13];
    float* out = (float*)d_out;

    int dev = 0, sms = 148;
    cudaGetDevice(&dev);
    cudaDeviceGetAttribute(&sms, cudaDevAttrMultiProcessorCount, dev);
    if (sms <= 0) sms = 148;

    cudaFuncSetAttribute(tgn_kernel, cudaFuncAttributeMaxDynamicSharedMemorySize, SMEM_BYTES);

    tgn_kernel<<<sms, NT, SMEM_BYTES>>>(src, dst, ef, ts, mem0, lu0,
                                        W1, b1, W2, b2, wih, bih, whh, bhh, out);
}

// round 5
// speedup vs baseline: 6.4746x; 1.3779x over previous
#include <cuda_runtime.h>
#include <math.h>

#define NNODES 100000
#define BATCH  4096
#define MDIM   256
#define G3DIM  768
#define INENC  515
#define NT     512
#define BK     16

// ---------------- device scratch (rebuilt every launch; graph-replay safe) -----------
__device__ int      g_ncnt[NNODES];
__device__ int      g_nbuck[NNODES * BK];
__device__ int      g_pred[2 * BATCH];
__device__ float    g_F[2 * BATCH];          // precomputed decay per endpoint
__device__ int      g_evlist[BATCH];
__device__ int      g_lvl_start[BATCH + 2];
__device__ int      g_nlevels;
__device__ unsigned g_bar_count = 0;
__device__ unsigned g_bar_gen   = 0;

// permuted (sorted-position) event metadata
__device__ int   g_pS[BATCH], g_pD[BATCH];
__device__ float g_pFs[BATCH], g_pFd[BATCH];
__device__ float g_pEF[BATCH * 3];

// inter-phase activations (indexed by sorted position)
__device__ float g_H1 [BATCH * MDIM];     // 4 MB
__device__ float g_GI [BATCH * G3DIM];    // 12 MB
__device__ float g_GHs[BATCH * G3DIM];    // 12 MB
__device__ float g_GHd[BATCH * G3DIM];    // 12 MB

// transposed+packed weights: layout [k4][c][4] (one float4 per (k4,c))
__device__ float g_W1tA[MDIM * MDIM];     // W1 cols [0,256)
__device__ float g_W1tB[MDIM * MDIM];     // W1 cols [256,512)
__device__ float g_W1te[3 * MDIM];        // W1 ef tail, [k][c]
__device__ float g_whht[G3DIM * MDIM];
__device__ float g_Wct [G3DIM * MDIM];    // Wc = wih @ W2, packed
__device__ float g_bc  [G3DIM];           // bih + wih @ b2

// ---------------- software grid barrier (1 block/SM) ---------------------------------
__device__ __forceinline__ void grid_sync() {
    __syncthreads();
    if (threadIdx.x == 0) {
        __threadfence();
        unsigned gen = *((volatile unsigned*)&g_bar_gen);
        if (atomicAdd(&g_bar_count, 1u) == gridDim.x - 1u) {
            *((volatile unsigned*)&g_bar_count) = 0u;
            __threadfence();
            atomicAdd(&g_bar_gen, 1u);
        } else {
            while (*((volatile unsigned*)&g_bar_gen) == gen) { __nanosleep(64); }
        }
        __threadfence();
    }
    __syncthreads();
}

// ---------------- shared memory layouts ----------------------------------------------
struct TileSm {
    float Xa[16][MDIM];
    float Xb[16][MDIM];
    float EF[16][4];
};
struct LvlS {
    int level[BATCH];
    int off[BATCH + 2];
    int cnt[BATCH + 2];
    int maxl;
    int changed;
};
#define SMEM_BYTES ((int)(sizeof(LvlS) > sizeof(TileSm) ? sizeof(LvlS) : sizeof(TileSm)))

extern __shared__ __align__(16) char smem_raw[];

__device__ __forceinline__ float sigmoidf_(float x) { return 1.0f / (1.0f + expf(-x)); }

__device__ __forceinline__ float dot4(float4 a, float4 b, float acc) {
    acc = fmaf(a.x, b.x, acc);
    acc = fmaf(a.y, b.y, acc);
    acc = fmaf(a.z, b.z, acc);
    acc = fmaf(a.w, b.w, acc);
    return acc;
}

// ---------------- per-level phase-parallel pipeline ----------------------------------
// R = rows per thread-group; tile height = 2*R events.
template<int R>
__device__ void run_level(int lvS, int lvE,
                          const float* __restrict__ b1,
                          const float* __restrict__ bhh,
                          float* __restrict__ out)
{
    const int TMR = 2 * R;
    const int tid = threadIdx.x;
    const int nE = lvE - lvS;
    const int nchunk = (nE + TMR - 1) / TMR;
    TileSm* Sx = (TileSm*)smem_raw;
    const float4* w1a4 = (const float4*)g_W1tA;
    const float4* w1b4 = (const float4*)g_W1tB;
    const float4* whh4 = (const float4*)g_whht;
    const float4* wct4 = (const float4*)g_Wct;

    // ---- P1: H1 (type 0) + GHs (types 1-3) + GHd (types 4-6)
    for (int u = blockIdx.x; u < 7 * nchunk; u += gridDim.x) {
        int chunk = u / 7, type = u - chunk * 7;
        int base = lvS + chunk * TMR;
        int cnt = min(TMR, lvE - base);
        __syncthreads();
        if (type == 0) {
            for (int i = tid; i < TMR * MDIM; i += NT) {
                int m = i >> 8, c = i & 255;
                float xs = 0.f, xd = 0.f;
                if (m < cnt) {
                    int p = base + m;
                    xs = out[(size_t)g_pS[p] * MDIM + c] * g_pFs[p];
                    xd = out[(size_t)g_pD[p] * MDIM + c] * g_pFd[p];
                }
                Sx->Xa[m][c] = xs;
                Sx->Xb[m][c] = xd;
            }
            if (tid < TMR) {
                int m = tid;
                float e0 = 0.f, e1 = 0.f, e2 = 0.f;
                if (m < cnt) {
                    int p = base + m;
                    e0 = g_pEF[3 * p]; e1 = g_pEF[3 * p + 1]; e2 = g_pEF[3 * p + 2];
                }
                Sx->EF[m][0] = e0; Sx->EF[m][1] = e1; Sx->EF[m][2] = e2; Sx->EF[m][3] = 0.f;
            }
            __syncthreads();
            int c = tid & 255, m0 = (tid >> 8) * R;
            float acc[R];
            float bb = b1[c];
            #pragma unroll
            for (int r = 0; r < R; r++) acc[r] = bb;
            #pragma unroll 4
            for (int k4 = 0; k4 < 64; k4++) {
                float4 wv = w1a4[k4 * MDIM + c];
                #pragma unroll
                for (int r = 0; r < R; r++)
                    acc[r] = dot4(((const float4*)Sx->Xa[m0 + r])[k4], wv, acc[r]);
            }
            #pragma unroll 4
            for (int k4 = 0; k4 < 64; k4++) {
                float4 wv = w1b4[k4 * MDIM + c];
                #pragma unroll
                for (int r = 0; r < R; r++)
                    acc[r] = dot4(((const float4*)Sx->Xb[m0 + r])[k4], wv, acc[r]);
            }
            #pragma unroll
            for (int k = 0; k < 3; k++) {
                float wv = g_W1te[k * MDIM + c];
                #pragma unroll
                for (int r = 0; r < R; r++) acc[r] = fmaf(Sx->EF[m0 + r][k], wv, acc[r]);
            }
            #pragma unroll
            for (int r = 0; r < R; r++)
                if (m0 + r < cnt)
                    g_H1[(size_t)(base + m0 + r) * MDIM + c] = fmaxf(acc[r], 0.f);
        } else {
            int t = type - 1;
            int isD = t >= 3;
            int cb = isD ? (t - 3) : t;
            for (int i = tid; i < TMR * MDIM; i += NT) {
                int m = i >> 8, c = i & 255;
                float x = 0.f;
                if (m < cnt) {
                    int p = base + m;
                    x = isD ? out[(size_t)g_pD[p] * MDIM + c] * g_pFd[p]
                            : out[(size_t)g_pS[p] * MDIM + c] * g_pFs[p];
                }
                Sx->Xa[m][c] = x;
            }
            __syncthreads();
            int cl = tid & 255, m0 = (tid >> 8) * R;
            int c = cb * MDIM + cl;
            float acc[R];
            float bb = bhh[c];
            #pragma unroll
            for (int r = 0; r < R; r++) acc[r] = bb;
            #pragma unroll 4
            for (int k4 = 0; k4 < 64; k4++) {
                float4 wv = whh4[k4 * G3DIM + c];
                #pragma unroll
                for (int r = 0; r < R; r++)
                    acc[r] = dot4(((const float4*)Sx->Xa[m0 + r])[k4], wv, acc[r]);
            }
            float* dstGH = isD ? g_GHd : g_GHs;
            #pragma unroll
            for (int r = 0; r < R; r++)
                if (m0 + r < cnt)
                    dstGH[(size_t)(base + m0 + r) * G3DIM + c] = acc[r];
        }
    }
    grid_sync();

    // ---- P2: GI = H1 @ Wc^T + bc  (3 col-blocks per chunk)
    for (int u = blockIdx.x; u < 3 * nchunk; u += gridDim.x) {
        int chunk = u / 3, cb = u - chunk * 3;
        int base = lvS + chunk * TMR;
        int cnt = min(TMR, lvE - base);
        __syncthreads();
        for (int i = tid; i < TMR * MDIM; i += NT) {
            int m = i >> 8, c = i & 255;
            Sx->Xa[m][c] = (m < cnt) ? g_H1[(size_t)(base + m) * MDIM + c] : 0.f;
        }
        __syncthreads();
        int cl = tid & 255, m0 = (tid >> 8) * R;
        int c = cb * MDIM + cl;
        float acc[R];
        float bb = g_bc[c];
        #pragma unroll
        for (int r = 0; r < R; r++) acc[r] = bb;
        #pragma unroll 4
        for (int k4 = 0; k4 < 64; k4++) {
            float4 wv = wct4[k4 * G3DIM + c];
            #pragma unroll
            for (int r = 0; r < R; r++)
                acc[r] = dot4(((const float4*)Sx->Xa[m0 + r])[k4], wv, acc[r]);
        }
        #pragma unroll
        for (int r = 0; r < R; r++)
            if (m0 + r < cnt)
                g_GI[(size_t)(base + m0 + r) * G3DIM + c] = acc[r];
    }
    grid_sync();

    // ---- P3: GRU elementwise + scatter (thread = (event, col))
    for (int idx = blockIdx.x * NT + tid; idx < nE * MDIM; idx += gridDim.x * NT) {
        int pl = idx >> 8, j = idx & 255;
        int p = lvS + pl;
        int s = g_pS[p], d = g_pD[p];
        float hs = out[(size_t)s * MDIM + j] * g_pFs[p];
        float hd = out[(size_t)d * MDIM + j] * g_pFd[p];
        const float* gi  = g_GI  + (size_t)p * G3DIM;
        const float* ghs = g_GHs + (size_t)p * G3DIM;
        const float* ghd = g_GHd + (size_t)p * G3DIM;
        float gir = gi[j], giz = gi[MDIM + j], gin = gi[2 * MDIM + j];
        float rr = sigmoidf_(gir + ghs[j]);
        float zz = sigmoidf_(giz + ghs[MDIM + j]);
        float nn = tanhf(gin + rr * ghs[2 * MDIM + j]);
        float us = (1.0f - zz) * nn + zz * hs;
        rr = sigmoidf_(gir + ghd[j]);
        zz = sigmoidf_(giz + ghd[MDIM + j]);
        nn = tanhf(gin + rr * ghd[2 * MDIM + j]);
        float ud = (1.0f - zz) * nn + zz * hd;
        if (s != d) out[(size_t)s * MDIM + j] = us;   // dst wins when s==d
        out[(size_t)d * MDIM + j] = ud;
    }
    grid_sync();
}

__global__ void __launch_bounds__(NT, 1)
tgn_kernel(const int* __restrict__ src, const int* __restrict__ dst,
           const float* __restrict__ ef, const int* __restrict__ ts,
           const float* __restrict__ mem0, const float* __restrict__ lu0,
           const float* __restrict__ W1, const float* __restrict__ b1,
           const float* __restrict__ W2, const float* __restrict__ b2,
           const float* __restrict__ wih, const float* __restrict__ bih,
           const float* __restrict__ whh, const float* __restrict__ bhh,
           float* __restrict__ out)
{
    const int tid     = threadIdx.x;
    const int gtid    = blockIdx.x * NT + tid;
    const int gstride = gridDim.x * NT;

    // ---------- Phase A: copy memory -> out; weight transforms; counters -------------
    {
        const float4* s4 = (const float4*)mem0;
        float4*       d4 = (float4*)out;
        const int n4 = NNODES * MDIM / 4;
        for (int i = gtid; i < n4; i += gstride) d4[i] = s4[i];
        for (int i = gtid; i < NNODES; i += gstride) g_ncnt[i] = 0;

        for (int i = gtid; i < MDIM * MDIM; i += gstride) {
            int k4 = i >> 10, rem = i & 1023, c = rem >> 2, ks = rem & 3;
            int k = k4 * 4 + ks;
            g_W1tA[i] = W1[(size_t)c * INENC + k];
            g_W1tB[i] = W1[(size_t)c * INENC + MDIM + k];
        }
        for (int i = gtid; i < G3DIM * MDIM; i += gstride) {
            int k4 = i / 3072, rem = i - k4 * 3072, c = rem >> 2, ks = rem & 3;
            int k = k4 * 4 + ks;
            g_whht[i] = whh[(size_t)c * MDIM + k];
        }
        for (int i = gtid; i < 3 * MDIM; i += gstride) {
            int k = i >> 8, c = i & 255;
            g_W1te[i] = W1[(size_t)c * INENC + 2 * MDIM + k];
        }
        // Wc = wih @ W2 (packed), bc = bih + wih @ b2
        for (int i = gtid; i < G3DIM * (MDIM / 4); i += gstride) {
            int c = i >> 6, k4 = i & 63;
            float4 a = make_float4(0.f, 0.f, 0.f, 0.f);
            const float*  wr  = wih + (size_t)c * MDIM;
            const float4* w2r = (const float4*)W2;
            for (int j = 0; j < MDIM; j++) {
                float wv = wr[j];
                float4 b = w2r[j * 64 + k4];
                a.x = fmaf(wv, b.x, a.x);
                a.y = fmaf(wv, b.y, a.y);
                a.z = fmaf(wv, b.z, a.z);
                a.w = fmaf(wv, b.w, a.w);
            }
            float* dstp = g_Wct + (size_t)k4 * 3072 + c * 4;
            dstp[0] = a.x; dstp[1] = a.y; dstp[2] = a.z; dstp[3] = a.w;
        }
        for (int c = gtid; c < G3DIM; c += gstride) {
            float acc = bih[c];
            const float* wr = wih + (size_t)c * MDIM;
            for (int j = 0; j < MDIM; j++) acc = fmaf(wr[j], b2[j], acc);
            g_bc[c] = acc;
        }
    }
    grid_sync();

    // ---------- Phase A2: per-node occurrence buckets ---------------------------------
    for (int i = gtid; i < 2 * BATCH; i += gstride) {
        int e = i >> 1;
        int v = (i & 1) ? dst[e] : src[e];
        int slot = atomicAdd(&g_ncnt[v], 1);
        if (slot < BK) g_nbuck[v * BK + slot] = i;
    }
    grid_sync();

    // ---------- Phase A3: predecessor endpoint + decay factor -------------------------
    for (int i = gtid; i < 2 * BATCH; i += gstride) {
        int e = i >> 1;
        int v = (i & 1) ? dst[e] : src[e];
        int lim = e << 1;
        int cmax = min(g_ncnt[v], BK);
        int p = -1;
        for (int t = 0; t < cmax; t++) {
            int j = g_nbuck[v * BK + t];
            if (j < lim && j > p) p = j;
        }
        g_pred[i] = p;
        float prev_t = (p >= 0) ? (float)ts[p >> 1] : lu0[v];
        float dt = fmaxf((float)ts[e] - prev_t, 0.f);
        g_F[i] = expf(-0.1f * dt);
    }
    grid_sync();

    // ---------- Phase B (block 0): levelize + sort + permuted metadata ----------------
    if (blockIdx.x == 0) {
        LvlS* L = (LvlS*)smem_raw;
        for (int e = tid; e < BATCH; e += NT) L->level[e] = 0;
        if (tid == 0) L->maxl = 0;
        __syncthreads();
        for (;;) {
            if (tid == 0) L->changed = 0;
            __syncthreads();
            for (int e = tid; e < BATCH; e += NT) {
                int ps = g_pred[2 * e], pd = g_pred[2 * e + 1];
                int lv = 0;
                if (ps >= 0) { int t = L->level[ps >> 1] + 1; if (t > lv) lv = t; }
                if (pd >= 0) { int t = L->level[pd >> 1] + 1; if (t > lv) lv = t; }
                if (lv > L->level[e]) { L->level[e] = lv; L->changed = 1; }
            }
            __syncthreads();
            int ch = L->changed;
            __syncthreads();
            if (!ch) break;
        }
        for (int e = tid; e < BATCH; e += NT) atomicMax(&L->maxl, L->level[e]);
        __syncthreads();
        int nl = L->maxl + 1;
        for (int i = tid; i < nl + 1; i += NT) L->cnt[i] = 0;
        __syncthreads();
        for (int e = tid; e < BATCH; e += NT) atomicAdd(&L->cnt[L->level[e]], 1);
        __syncthreads();
        if (tid == 0) {
            int acc = 0;
            for (int l = 0; l < nl; l++) { L->off[l] = acc; acc += L->cnt[l]; }
            L->off[nl] = acc;
            g_nlevels = nl;
            for (int l = 0; l <= nl; l++) g_lvl_start[l] = L->off[l];
        }
        __syncthreads();
        for (int i = tid; i < nl; i += NT) L->cnt[i] = 0;
        __syncthreads();
        for (int e = tid; e < BATCH; e += NT) {
            int l = L->level[e];
            int pos = L->off[l] + atomicAdd(&L->cnt[l], 1);
            g_evlist[pos] = e;
        }
        __syncthreads();
        // permuted metadata by sorted position
        for (int p = tid; p < BATCH; p += NT) {
            int e = g_evlist[p];
            g_pS[p] = src[e];
            g_pD[p] = dst[e];
            g_pFs[p] = g_F[2 * e];
            g_pFd[p] = g_F[2 * e + 1];
            g_pEF[3 * p]     = ef[3 * e];
            g_pEF[3 * p + 1] = ef[3 * e + 1];
            g_pEF[3 * p + 2] = ef[3 * e + 2];
        }
    }
    grid_sync();

    // ---------- Phase C: per-level phase-parallel pipeline ----------------------------
    const int nlevels = g_nlevels;
    for (int lvl = 0; lvl < nlevels; lvl++) {
        int lvS = g_lvl_start[lvl];
        int lvE = g_lvl_start[lvl + 1];
        if (lvE - lvS <= 32) run_level<2>(lvS, lvE, b1, bhh, out);
        else                 run_level<8>(lvS, lvE, b1, bhh, out);
    }
}

extern "C" void kernel_launch(void* const* d_in, const int* in_sizes, int n_in,
                              void* d_out, int out_size)
{
    const int*   src  = (const int*)  d_in[0];
    const int*   dst  = (const int*)  d_in[1];
    const float* ef   = (const float*)d_in[2];
    const int*   ts   = (const int*)  d_in[3];
    const float* mem0 = (const float*)d_in[4];
    const float* lu0  = (const float*)d_in[5];
    const float* W1   = (const float*)d_in[6];
    const float* b1   = (const float*)d_in[7];
    const float* W2   = (const float*)d_in[8];
    const float* b2   = (const float*)d_in[9];
    const float* wih  = (const float*)d_in[10];
    const float* whh  = (const float*)d_in[11];
    const float* bih  = (const float*)d_in[12];
    const float* bhh  = (const float*)d_in[13];
    float* out = (float*)d_out;

    int dev = 0, sms = 148;
    cudaGetDevice(&dev);
    cudaDeviceGetAttribute(&sms, cudaDevAttrMultiProcessorCount, dev);
    if (sms <= 0) sms = 148;

    cudaFuncSetAttribute(tgn_kernel, cudaFuncAttributeMaxDynamicSharedMemorySize, SMEM_BYTES);

    tgn_kernel<<<sms, NT, SMEM_BYTES>>>(src, dst, ef, ts, mem0, lu0,
                                        W1, b1, W2, b2, wih, bih, whh, bhh, out);
}